// round 9
// baseline (speedup 1.0000x reference)
#include <cuda_runtime.h>
#include <cstdint>

// Correlation: out[n,q,y,x] = (1/C) * sum_c d1[n,c,y,x] * d2pad[n,c,y+dy,x+dx]
// q = (dy+4)*9 + (dx+4). Shapes: N=8, C=256, H=96, W=160. Out (8,81,96,160) f32.
//
// R8: R3 scalar compute core (384 thr = 3 dy x 128, 4 px/thread, 36 accs)
// + 4-stage cp.async pipeline (KC=4), single __syncthreads per chunk,
// fully hoisted per-thread copy slots.

#define CC   256
#define HH   96
#define WW   160
#define NN   8

constexpr int TQX  = 8;    // float4 groups per tile in x -> 32 pixels
constexpr int TTY  = 16;   // tile rows
constexpr int KC   = 4;    // channels per chunk
constexpr int S1S  = 36;   // s1 row stride (floats)
constexpr int S2S  = 44;   // s2 row stride (floats)
constexpr int S2R  = 18;   // s2 rows (16 + 2)
constexpr int NT   = 384;
constexpr int NCH  = CC / KC;               // 64 chunks
constexpr int STAGES = 4;
constexpr int S1_F = KC * TTY * S1S;        // 2304 floats
constexpr int S2_F = KC * S2R * S2S;        // 3168 floats
constexpr int STAGE_F = S1_F + S2_F;        // 5472 floats (21888 B)
constexpr int SMEM_BYTES = STAGES * STAGE_F * 4;  // 87552 B
constexpr int CH_STRIDE = HH * WW;          // floats per channel

__device__ __forceinline__ void cp16(uint32_t dst, const void* src, bool p) {
    asm volatile("cp.async.cg.shared.global [%0], [%1], 16, %2;\n"
                 :: "r"(dst), "l"(src), "r"(p ? 16 : 0));
}
__device__ __forceinline__ void cp_commit() {
    asm volatile("cp.async.commit_group;\n" ::: "memory");
}
template <int N>
__device__ __forceinline__ void cp_wait() {
    asm volatile("cp.async.wait_group %0;\n" :: "n"(N) : "memory");
}

__global__ __launch_bounds__(NT, 2)
void corr_kernel(const float* __restrict__ d1,
                 const float* __restrict__ d2,
                 float* __restrict__ out)
{
    extern __shared__ float smem[];

    // blockIdx.x = g3 + 3*tile_x ; blockIdx.y = tile_y + 6*n
    const int g3  = blockIdx.x % 3;
    const int tlx = blockIdx.x / 3;
    const int ty0 = (blockIdx.y % 6) * TTY;
    const int n   = blockIdx.y / 6;
    const int x0  = tlx * (TQX * 4);

    const int t    = threadIdx.x;   // 0..383
    const int tsub = t / 128;       // dy within group
    const int tl   = t % 128;
    const int g    = tl % TQX;      // x-group (4 pixels)
    const int tyl  = tl / TQX;      // 0..15

    float acc[9][4];
#pragma unroll
    for (int dxi = 0; dxi < 9; dxi++)
#pragma unroll
        for (int p = 0; p < 4; p++) acc[dxi][p] = 0.f;

    const int dy_base = 3 * g3 - 4;
    const int yb      = ty0 + dy_base;
    const float* d1n = d1 + (size_t)n * CC * HH * WW;
    const float* d2n = d2 + (size_t)n * CC * HH * WW;

    const uint32_t smem_u32 = (uint32_t)__cvta_generic_to_shared(smem);

    // ---------- hoisted copy slots ----------
    // d1 tile per stage: KC*TTY*TQX = 512 float4.  slot A: i=t (all),
    // slot B: i=t+384 (t<128 -> cc=3).
    const int xg1a = t % TQX, yy1a = (t / TQX) % TTY, cc1a = t / 128;
    const float* p1a = d1n + (size_t)(cc1a * HH + ty0 + yy1a) * WW + x0 + xg1a * 4;
    const uint32_t dst1a = (uint32_t)(((cc1a * TTY + yy1a) * S1S + xg1a * 4) * 4);

    const bool ok1b = (t < 128);
    const int xg1b = t % TQX, yy1b = t / TQX;            // cc = 3
    const float* p1b = d1n + (size_t)(3 * HH + ty0 + yy1b) * WW + x0 + xg1b * 4;
    const uint32_t dst1b = (uint32_t)((((3 * TTY) + yy1b) * S1S + xg1b * 4) * 4);

    // d2 tile per stage: KC*S2R*10 = 720 float4.  slot A: i=t (all),
    // slot B: i=t+384 (t<336).
    const int xg2a = t % 10, rr2a = (t / 10) % S2R, cc2a = t / 180;
    const int gy2a = yb + rr2a, gx2a = x0 - 4 + xg2a * 4;
    const bool ok2a = gy2a >= 0 && gy2a < HH && gx2a >= 0 && gx2a + 3 < WW;
    const float* p2a = ok2a ? d2n + (size_t)(cc2a * HH + gy2a) * WW + gx2a : d2n;
    const uint32_t dst2a =
        (uint32_t)(S1_F * 4 + ((cc2a * S2R + rr2a) * S2S + xg2a * 4) * 4);

    const bool v2b = (t < 336);
    const int i2b = t + 384;
    const int xg2b = i2b % 10, rr2b = (i2b / 10) % S2R, cc2b = i2b / 180;
    const int gy2b = yb + rr2b, gx2b = x0 - 4 + xg2b * 4;
    const bool ok2b = v2b && gy2b >= 0 && gy2b < HH && gx2b >= 0 && gx2b + 3 < WW;
    const float* p2b = ok2b ? d2n + (size_t)(cc2b * HH + gy2b) * WW + gx2b : d2n;
    const uint32_t dst2b =
        (uint32_t)(S1_F * 4 + ((cc2b * S2R + rr2b) * S2S + xg2b * 4) * 4);

    // running pointers (advance KC channels per stage load)
    const float* q1a = p1a; const float* q1b = p1b;
    const float* q2a = p2a; const float* q2b = p2b;

    auto load_stage = [&](int stage) {
        const uint32_t sb = smem_u32 + (uint32_t)(stage * (STAGE_F * 4));
        cp16(sb + dst1a, q1a, true);
        if (ok1b) cp16(sb + dst1b, q1b, true);
        cp16(sb + dst2a, q2a, ok2a);
        if (v2b)  cp16(sb + dst2b, q2b, ok2b);
        q1a += KC * CH_STRIDE; q1b += KC * CH_STRIDE;
        q2a += KC * CH_STRIDE; q2b += KC * CH_STRIDE;
        cp_commit();
    };

    // ---------- prologue: fill STAGES-1 stages ----------
#pragma unroll
    for (int s = 0; s < STAGES - 1; s++) load_stage(s);

    // ---------- mainloop: one barrier per chunk ----------
    for (int it = 0; it < NCH; it++) {
        cp_wait<STAGES - 2>();   // chunk `it` resident
        __syncthreads();         // visible to all warps

        const float* s1c = smem + (it % STAGES) * STAGE_F;
        const float* s2c = s1c + S1_F;

#pragma unroll
        for (int c = 0; c < KC; c++) {
            const float4 a = *reinterpret_cast<const float4*>(
                &s1c[(c * TTY + tyl) * S1S + g * 4]);
            float b[12];
#pragma unroll
            for (int k = 0; k < 3; k++) {
                float4 w = *reinterpret_cast<const float4*>(
                    &s2c[(c * S2R + tyl + tsub) * S2S + g * 4 + k * 4]);
                b[k * 4 + 0] = w.x; b[k * 4 + 1] = w.y;
                b[k * 4 + 2] = w.z; b[k * 4 + 3] = w.w;
            }
#pragma unroll
            for (int dxi = 0; dxi < 9; dxi++) {
                acc[dxi][0] = fmaf(a.x, b[dxi + 0], acc[dxi][0]);
                acc[dxi][1] = fmaf(a.y, b[dxi + 1], acc[dxi][1]);
                acc[dxi][2] = fmaf(a.z, b[dxi + 2], acc[dxi][2]);
                acc[dxi][3] = fmaf(a.w, b[dxi + 3], acc[dxi][3]);
            }
        }

        // prefetch chunk it+STAGES-1 into the buffer consumed at iter it-1
        // (safe: all warps passed the barrier above, so iter it-1 is done)
        if (it + STAGES - 1 < NCH) load_stage((it + STAGES - 1) % STAGES);
        else cp_commit();        // keep wait_group accounting exact
    }

    // ---------- epilogue ----------
    const float inv = 1.0f / (float)CC;
    const int y  = ty0 + tyl;
    const int xo = x0 + g * 4;
    const int dy = dy_base + tsub;
#pragma unroll
    for (int dxi = 0; dxi < 9; dxi++) {
        int q = (dy + 4) * 9 + dxi;
        float4 v = make_float4(acc[dxi][0] * inv, acc[dxi][1] * inv,
                               acc[dxi][2] * inv, acc[dxi][3] * inv);
        *reinterpret_cast<float4*>(
            out + (((size_t)n * 81 + q) * HH + y) * WW + xo) = v;
    }
}

extern "C" void kernel_launch(void* const* d_in, const int* in_sizes, int n_in,
                              void* d_out, int out_size)
{
    const float* data1 = (const float*)d_in[0];
    const float* data2 = (const float*)d_in[1];
    float* out = (float*)d_out;

    cudaFuncSetAttribute(corr_kernel,
                         cudaFuncAttributeMaxDynamicSharedMemorySize,
                         SMEM_BYTES);

    dim3 grid(3 * (WW / (TQX * 4)), (HH / TTY) * NN, 1);  // (15, 48)
    dim3 block(NT, 1, 1);
    corr_kernel<<<grid, block, SMEM_BYTES>>>(data1, data2, out);
}

// round 11
// speedup vs baseline: 1.3773x; 1.3773x over previous
#include <cuda_runtime.h>
#include <cstdint>

// Correlation: out[n,q,y,x] = (1/C) * sum_c d1[n,c,y,x] * d2pad[n,c,y+dy,x+dx]
// q = (dy+4)*9 + (dx+4). Shapes: N=8, C=256, H=96, W=160. Out (8,81,96,160) f32.
//
// R10: scalar 8 px/thread (72 float accs), 192-thr blocks = 3 dy x 64,
// KC=8 2-stage cp.async pipeline (R3 shape), hoisted 2-slot copy addressing.

#define CC   256
#define HH   96
#define WW   160
#define NN   8

constexpr int TX   = 32;   // tile width in pixels
constexpr int TTY  = 16;   // tile rows
constexpr int KC   = 8;    // channels per smem chunk
constexpr int S1S  = 36;   // s1 row stride (floats), 32 used
constexpr int S2S  = 44;   // s2 row stride (floats), 40 used
constexpr int S2R  = 18;   // s2 rows (16 + 2)
constexpr int NT   = 192;
constexpr int NCH  = CC / KC;               // 32 chunks
constexpr int S1_F = KC * TTY * S1S;        // 4608
constexpr int S2_F = KC * S2R * S2S;        // 6336
constexpr int STAGE_F = S1_F + S2_F;        // 10944
constexpr int SMEM_BYTES = 2 * STAGE_F * 4; // 87552
constexpr int CH_STRIDE = HH * WW;

__device__ __forceinline__ void cp16(uint32_t dst, const void* src, bool p) {
    asm volatile("cp.async.cg.shared.global [%0], [%1], 16, %2;\n"
                 :: "r"(dst), "l"(src), "r"(p ? 16 : 0));
}
__device__ __forceinline__ void cp_commit() {
    asm volatile("cp.async.commit_group;\n" ::: "memory");
}
template <int N>
__device__ __forceinline__ void cp_wait() {
    asm volatile("cp.async.wait_group %0;\n" :: "n"(N) : "memory");
}

__global__ __launch_bounds__(NT, 2)
void corr_kernel(const float* __restrict__ d1,
                 const float* __restrict__ d2,
                 float* __restrict__ out)
{
    extern __shared__ float smem[];

    // blockIdx.x = g3 + 3*tile_x ; blockIdx.y = tile_y + 6*n
    const int g3  = blockIdx.x % 3;
    const int tlx = blockIdx.x / 3;
    const int ty0 = (blockIdx.y % 6) * TTY;
    const int n   = blockIdx.y / 6;
    const int x0  = tlx * TX;

    const int t    = threadIdx.x;   // 0..191
    const int tsub = t / 64;        // dy within group
    const int tl   = t % 64;
    const int g    = tl % 4;        // x-group of 8 pixels
    const int tyl  = tl / 4;        // 0..15

    float acc[9][8];
#pragma unroll
    for (int dxi = 0; dxi < 9; dxi++)
#pragma unroll
        for (int p = 0; p < 8; p++) acc[dxi][p] = 0.f;

    const int dy_base = 3 * g3 - 4;
    const int yb      = ty0 + dy_base;
    const float* d1n = d1 + (size_t)n * CC * HH * WW;
    const float* d2n = d2 + (size_t)n * CC * HH * WW;

    const uint32_t smem_u32 = (uint32_t)__cvta_generic_to_shared(smem);

    // ---- hoisted copy slots (one d1 + one d2 float4 per channel) ----
    const bool ok1 = (t < 128);
    const int  yy1 = (t >> 3) & 15;
    const int  xg1 = t & 7;
    const float* s1p = d1n + (size_t)(ty0 + yy1) * WW + x0 + xg1 * 4;
    const uint32_t dst1 = (uint32_t)((yy1 * S1S + xg1 * 4) * 4);

    const bool v2  = (t < 180);
    const int  rr2 = t / 10;
    const int  xg2 = t % 10;
    const int  gy2 = yb + rr2;
    const int  gx2 = x0 - 4 + xg2 * 4;
    const bool ok2 = v2 && gy2 >= 0 && gy2 < HH && gx2 >= 0 && gx2 + 3 < WW;
    const float* s2p = ok2 ? d2n + (size_t)gy2 * WW + gx2 : d2n;
    const uint32_t dst2 = (uint32_t)((rr2 * S2S + xg2 * 4) * 4);

    auto load_stage = [&](int stage) {
        const uint32_t sb  = smem_u32 + (uint32_t)(stage * (STAGE_F * 4));
        const uint32_t s1b = sb + dst1;
        const uint32_t s2b = sb + (uint32_t)(S1_F * 4) + dst2;
#pragma unroll
        for (int cc = 0; cc < KC; cc++) {
            if (ok1) cp16(s1b + (uint32_t)(cc * (TTY * S1S * 4)), s1p, true);
            if (v2)  cp16(s2b + (uint32_t)(cc * (S2R * S2S * 4)), s2p, ok2);
            s1p += CH_STRIDE;
            s2p += CH_STRIDE;
        }
        cp_commit();
    };

    // ---- pipeline (R3 shape: 2-stage, load-next then wait) ----
    load_stage(0);

    int stage = 0;
    for (int it = 0; it < NCH; it++) {
        if (it + 1 < NCH) {
            load_stage(stage ^ 1);
            cp_wait<1>();
        } else {
            cp_wait<0>();
        }
        __syncthreads();

        const float* s1c = smem + stage * STAGE_F;
        const float* s2c = s1c + S1_F;

#pragma unroll
        for (int c = 0; c < KC; c++) {
            const float* arow = &s1c[(c * TTY + tyl) * S1S + g * 8];
            const float4 a0 = *reinterpret_cast<const float4*>(arow);
            const float4 a1 = *reinterpret_cast<const float4*>(arow + 4);
            const float a[8] = {a0.x, a0.y, a0.z, a0.w, a1.x, a1.y, a1.z, a1.w};

            const float* brow = &s2c[(c * S2R + tyl + tsub) * S2S + g * 8];
            const float4 b0 = *reinterpret_cast<const float4*>(brow);
            const float4 b1 = *reinterpret_cast<const float4*>(brow + 4);
            const float4 b2 = *reinterpret_cast<const float4*>(brow + 8);
            const float4 b3 = *reinterpret_cast<const float4*>(brow + 12);
            const float b[16] = {b0.x, b0.y, b0.z, b0.w, b1.x, b1.y, b1.z, b1.w,
                                 b2.x, b2.y, b2.z, b2.w, b3.x, b3.y, b3.z, b3.w};

#pragma unroll
            for (int dxi = 0; dxi < 9; dxi++) {
#pragma unroll
                for (int p = 0; p < 8; p++)
                    acc[dxi][p] = fmaf(a[p], b[dxi + p], acc[dxi][p]);
            }
        }
        __syncthreads();
        stage ^= 1;
    }

    // ---- epilogue ----
    const float inv = 1.0f / (float)CC;
    const int y  = ty0 + tyl;
    const int xo = x0 + g * 8;
    const int dy = dy_base + tsub;
#pragma unroll
    for (int dxi = 0; dxi < 9; dxi++) {
        const int q = (dy + 4) * 9 + dxi;
        float* op = out + (((size_t)n * 81 + q) * HH + y) * WW + xo;
        *reinterpret_cast<float4*>(op) =
            make_float4(acc[dxi][0] * inv, acc[dxi][1] * inv,
                        acc[dxi][2] * inv, acc[dxi][3] * inv);
        *reinterpret_cast<float4*>(op + 4) =
            make_float4(acc[dxi][4] * inv, acc[dxi][5] * inv,
                        acc[dxi][6] * inv, acc[dxi][7] * inv);
    }
}

extern "C" void kernel_launch(void* const* d_in, const int* in_sizes, int n_in,
                              void* d_out, int out_size)
{
    const float* data1 = (const float*)d_in[0];
    const float* data2 = (const float*)d_in[1];
    float* out = (float*)d_out;

    cudaFuncSetAttribute(corr_kernel,
                         cudaFuncAttributeMaxDynamicSharedMemorySize,
                         SMEM_BYTES);

    dim3 grid(3 * (WW / TX), (HH / TTY) * NN, 1);  // (15, 48)
    dim3 block(NT, 1, 1);
    corr_kernel<<<grid, block, SMEM_BYTES>>>(data1, data2, out);
}

// round 12
// speedup vs baseline: 1.4489x; 1.0520x over previous
#include <cuda_runtime.h>
#include <cstdint>

// Correlation: out[n,q,y,x] = (1/C) * sum_c d1[n,c,y,x] * d2pad[n,c,y+dy,x+dx]
// q = (dy+4)*9 + (dx+4). Shapes: N=8, C=256, H=96, W=160. Out (8,81,96,160) f32.
//
// R12: R3 tile/pipeline (384 thr = 3 dy x 128, 4 px/thread, KC=8 2-stage
// cp.async) with f32x2 packed math: 18 u64 accumulators (36 regs, same as
// R3's 36 scalars), aligned pairs free from ulonglong2 loads, 5 packs/chan.
// Hoisted R10-style copy slots.

#define CC   256
#define HH   96
#define WW   160
#define NN   8

constexpr int TQX  = 8;    // float4 x-groups per tile -> 32 px
constexpr int TTY  = 16;   // tile rows
constexpr int KC   = 8;    // channels per smem chunk
constexpr int S1S  = 36;   // s1 row stride (floats)
constexpr int S2S  = 44;   // s2 row stride (floats)
constexpr int S2R  = 18;   // s2 rows (16 + 2)
constexpr int NT   = 384;
constexpr int NCH  = CC / KC;               // 32 chunks
constexpr int S1_F = KC * TTY * S1S;        // 4608
constexpr int S2_F = KC * S2R * S2S;        // 6336
constexpr int STAGE_F = S1_F + S2_F;        // 10944
constexpr int SMEM_BYTES = 2 * STAGE_F * 4; // 87552
constexpr int CH_STRIDE = HH * WW;

typedef unsigned long long u64;

__device__ __forceinline__ void cp16(uint32_t dst, const void* src, bool p) {
    asm volatile("cp.async.cg.shared.global [%0], [%1], 16, %2;\n"
                 :: "r"(dst), "l"(src), "r"(p ? 16 : 0));
}
__device__ __forceinline__ void cp_commit() {
    asm volatile("cp.async.commit_group;\n" ::: "memory");
}
template <int N>
__device__ __forceinline__ void cp_wait() {
    asm volatile("cp.async.wait_group %0;\n" :: "n"(N) : "memory");
}
__device__ __forceinline__ u64 pk(float lo, float hi) {
    u64 r;
    asm("mov.b64 %0, {%1, %2};" : "=l"(r) : "f"(lo), "f"(hi));
    return r;
}
__device__ __forceinline__ void upk(u64 v, float& lo, float& hi) {
    asm("mov.b64 {%0, %1}, %2;" : "=f"(lo), "=f"(hi) : "l"(v));
}
__device__ __forceinline__ void fma2(u64& acc, u64 a, u64 b) {
    asm("fma.rn.f32x2 %0, %1, %2, %0;" : "+l"(acc) : "l"(a), "l"(b));
}

__global__ __launch_bounds__(NT, 2)
void corr_kernel(const float* __restrict__ d1,
                 const float* __restrict__ d2,
                 float* __restrict__ out)
{
    extern __shared__ float smem[];

    // blockIdx.x = g3 + 3*tile_x ; blockIdx.y = tile_y + 6*n
    const int g3  = blockIdx.x % 3;
    const int tlx = blockIdx.x / 3;
    const int ty0 = (blockIdx.y % 6) * TTY;
    const int n   = blockIdx.y / 6;
    const int x0  = tlx * (TQX * 4);

    const int t    = threadIdx.x;   // 0..383
    const int tsub = t / 128;       // dy within group
    const int tl   = t % 128;
    const int g    = tl % TQX;      // x-group (4 px)
    const int tyl  = tl / TQX;      // 0..15

    u64 acc[9][2];
#pragma unroll
    for (int dxi = 0; dxi < 9; dxi++) {
        acc[dxi][0] = 0ull;
        acc[dxi][1] = 0ull;
    }

    const int dy_base = 3 * g3 - 4;
    const int yb      = ty0 + dy_base;
    const float* d1n = d1 + (size_t)n * CC * HH * WW;
    const float* d2n = d2 + (size_t)n * CC * HH * WW;

    const uint32_t smem_u32 = (uint32_t)__cvta_generic_to_shared(smem);

    // ---- hoisted copy slots (R10 style): one d1 + one d2 float4 per channel ----
    const bool ok1 = (t < 128);                 // 128 float4 per d1 channel
    const int  yy1 = (t >> 3) & 15;
    const int  xg1 = t & 7;
    const float* s1p = d1n + (size_t)(ty0 + yy1) * WW + x0 + xg1 * 4;
    const uint32_t dst1 = (uint32_t)((yy1 * S1S + xg1 * 4) * 4);

    const bool v2  = (t < 180);                 // 180 float4 per d2 channel
    const int  rr2 = t / 10;
    const int  xg2 = t % 10;
    const int  gy2 = yb + rr2;
    const int  gx2 = x0 - 4 + xg2 * 4;
    const bool ok2 = v2 && gy2 >= 0 && gy2 < HH && gx2 >= 0 && gx2 + 3 < WW;
    const float* s2p = ok2 ? d2n + (size_t)gy2 * WW + gx2 : d2n;
    const uint32_t dst2 = (uint32_t)((rr2 * S2S + xg2 * 4) * 4);

    auto load_stage = [&](int stage) {
        const uint32_t sb  = smem_u32 + (uint32_t)(stage * (STAGE_F * 4));
        const uint32_t s1b = sb + dst1;
        const uint32_t s2b = sb + (uint32_t)(S1_F * 4) + dst2;
#pragma unroll
        for (int cc = 0; cc < KC; cc++) {
            if (ok1) cp16(s1b + (uint32_t)(cc * (TTY * S1S * 4)), s1p, true);
            if (v2)  cp16(s2b + (uint32_t)(cc * (S2R * S2S * 4)), s2p, ok2);
            s1p += CH_STRIDE;
            s2p += CH_STRIDE;
        }
        cp_commit();
    };

    // ---- pipeline (R3 shape) ----
    load_stage(0);

    int stage = 0;
    for (int it = 0; it < NCH; it++) {
        if (it + 1 < NCH) {
            load_stage(stage ^ 1);
            cp_wait<1>();
        } else {
            cp_wait<0>();
        }
        __syncthreads();

        const float* s1c = smem + stage * STAGE_F;
        const float* s2c = s1c + S1_F;

#pragma unroll
        for (int c = 0; c < KC; c++) {
            const ulonglong2 A = *reinterpret_cast<const ulonglong2*>(
                &s1c[(c * TTY + tyl) * S1S + g * 4]);
            const u64 ap[2] = {A.x, A.y};

            const float* brow = &s2c[(c * S2R + tyl + tsub) * S2S + g * 4];
            const ulonglong2 B0 = *reinterpret_cast<const ulonglong2*>(brow);
            const ulonglong2 B1 = *reinterpret_cast<const ulonglong2*>(brow + 4);
            const ulonglong2 B2 = *reinterpret_cast<const ulonglong2*>(brow + 8);
            const u64 e[6] = {B0.x, B0.y, B1.x, B1.y, B2.x, B2.y};
            u64 o[5];
#pragma unroll
            for (int k = 0; k < 5; k++) {
                float l0, h0, l1, h1;
                upk(e[k], l0, h0);
                upk(e[k + 1], l1, h1);
                o[k] = pk(h0, l1);
            }
#pragma unroll
            for (int dxi = 0; dxi < 9; dxi++) {
#pragma unroll
                for (int pp = 0; pp < 2; pp++) {
                    const int idx = dxi + 2 * pp;   // 0..10
                    const u64 bb = (idx & 1) ? o[idx >> 1] : e[idx >> 1];
                    fma2(acc[dxi][pp], ap[pp], bb);
                }
            }
        }
        __syncthreads();
        stage ^= 1;
    }

    // ---- epilogue ----
    const float inv = 1.0f / (float)CC;
    const int y  = ty0 + tyl;
    const int xo = x0 + g * 4;
    const int dy = dy_base + tsub;
#pragma unroll
    for (int dxi = 0; dxi < 9; dxi++) {
        const int q = (dy + 4) * 9 + dxi;
        float f0, f1, f2, f3;
        upk(acc[dxi][0], f0, f1);
        upk(acc[dxi][1], f2, f3);
        *reinterpret_cast<float4*>(
            out + (((size_t)n * 81 + q) * HH + y) * WW + xo) =
            make_float4(f0 * inv, f1 * inv, f2 * inv, f3 * inv);
    }
}

extern "C" void kernel_launch(void* const* d_in, const int* in_sizes, int n_in,
                              void* d_out, int out_size)
{
    const float* data1 = (const float*)d_in[0];
    const float* data2 = (const float*)d_in[1];
    float* out = (float*)d_out;

    cudaFuncSetAttribute(corr_kernel,
                         cudaFuncAttributeMaxDynamicSharedMemorySize,
                         SMEM_BYTES);

    dim3 grid(3 * (WW / (TQX * 4)), (HH / TTY) * NN, 1);  // (15, 48)
    dim3 block(NT, 1, 1);
    corr_kernel<<<grid, block, SMEM_BYTES>>>(data1, data2, out);
}